// round 15
// baseline (speedup 1.0000x reference)
#include <cuda_runtime.h>
#include <cuda_fp16.h>
#include <mma.h>

using namespace nvcuda;

#define NU 100000
#define NI 50000
#define NV 150000
#define D  64
#define NE 1000000
#define NL 3

#define CHUNK 1024
#define PBU ((NU + CHUNK - 1) / CHUNK)   // 98
#define PBI ((NI + CHUNK - 1) / CHUNK)   // 49
#define NPART (PBU + PBI)                // 147

#define FILL_BLOCKS ((NE + 255) / 256)       // 3907
#define INIT_BLOCKS ((NV * 16 + 255) / 256)  // 9375

// ---------------- static device scratch ----------------
__device__ float d_X[NV * D];      // current layer embeddings (fp32)
__device__ float d_acc[NV * D];    // running sum of layer embeddings
__device__ uint4 d_Xh4[NV * 8];    // X * dv_isqrt (fp16 rows)
__device__ uint4 d_Sh4[NV * 8];    // mid-hop: E(items) [0..NI), F(users) [NI..NV)
__device__ int   d_deg_u[NU], d_deg_i[NI];   // zero-init (BSS); k_down re-zeroes after use
__device__ float d_du_isqrt[NU], d_du_inv[NU];
__device__ float d_di_isqrt[NI], d_di_inv[NI];
__device__ int   d_rpu[NU + 1], d_rpi[NI + 1];
__device__ int   d_curu[NU], d_curi[NI];
__device__ int   d_colu[NE];       // items, grouped by user
__device__ int   d_coli[NE];       // users, grouped by item
__device__ int   d_part[256];

#define d_Xh ((uint2*)d_Xh4)

// ---------------- helpers ----------------
__device__ __forceinline__ float4 h4_to_f4(uint2 q) {
    __half2 h0 = *(__half2*)&q.x;
    __half2 h1 = *(__half2*)&q.y;
    float2 f0 = __half22float2(h0);
    float2 f1 = __half22float2(h1);
    return make_float4(f0.x, f0.y, f1.x, f1.y);
}
__device__ __forceinline__ uint2 f4_to_h4(float4 f) {
    __half2 h0 = __floats2half2_rn(f.x, f.y);
    __half2 h1 = __floats2half2_rn(f.z, f.w);
    uint2 q;
    q.x = *(unsigned*)&h0;
    q.y = *(unsigned*)&h1;
    return q;
}
__device__ __forceinline__ void h8_acc(uint4 q, float4& lo, float4& hi) {
    __half2* h = (__half2*)&q;
    float2 f0 = __half22float2(h[0]);
    float2 f1 = __half22float2(h[1]);
    float2 f2 = __half22float2(h[2]);
    float2 f3 = __half22float2(h[3]);
    lo.x += f0.x; lo.y += f0.y; lo.z += f1.x; lo.w += f1.y;
    hi.x += f2.x; hi.y += f2.y; hi.z += f3.x; hi.w += f3.y;
}
__device__ __forceinline__ uint4 f8_to_h8(float4 lo, float4 hi) {
    uint4 q;
    __half2 h0 = __floats2half2_rn(lo.x, lo.y);
    __half2 h1 = __floats2half2_rn(lo.z, lo.w);
    __half2 h2 = __floats2half2_rn(hi.x, hi.y);
    __half2 h3 = __floats2half2_rn(hi.z, hi.w);
    q.x = *(unsigned*)&h0; q.y = *(unsigned*)&h1;
    q.z = *(unsigned*)&h2; q.w = *(unsigned*)&h3;
    return q;
}

// ---------------- setup ----------------
// 2 edges per thread, int2 loads
__global__ void k_degree(const int* __restrict__ eu, const int* __restrict__ ei) {
    int p = blockIdx.x * blockDim.x + threadIdx.x;
    if (p < NE / 2) {
        int2 u2 = __ldg(&((const int2*)eu)[p]);
        int2 i2 = __ldg(&((const int2*)ei)[p]);
        atomicAdd(&d_deg_u[u2.x], 1);
        atomicAdd(&d_deg_u[u2.y], 1);
        atomicAdd(&d_deg_i[i2.x], 1);
        atomicAdd(&d_deg_i[i2.y], 1);
    }
}

__global__ void k_part() {
    int b = blockIdx.x;
    const int* deg; int n; int cb;
    if (b < PBU) { deg = d_deg_u; n = NU; cb = b; }
    else         { deg = d_deg_i; n = NI; cb = b - PBU; }
    int base = cb * CHUNK;
    int t = threadIdx.x;
    int tsum = 0;
    #pragma unroll
    for (int j = 0; j < 4; j++) {
        int idx = base + t * 4 + j;
        if (idx < n) tsum += deg[idx];
    }
    #pragma unroll
    for (int m = 16; m >= 1; m >>= 1) tsum += __shfl_xor_sync(0xffffffffu, tsum, m);
    __shared__ int sw[8];
    if ((t & 31) == 0) sw[t >> 5] = tsum;
    __syncthreads();
    if (t == 0) {
        int s = 0;
        #pragma unroll
        for (int w = 0; w < 8; w++) s += sw[w];
        d_part[b] = s;
    }
}

// k_down with inline segment-prefix of the partials; zeroes deg after use
__global__ void k_down() {
    int b = blockIdx.x;
    const int* deg; int* degw; int* rp; int* cur; float* isq; float* inv; int n; int cb; int segbase;
    if (b < PBU) { deg = d_deg_u; degw = d_deg_u; rp = d_rpu; cur = d_curu; isq = d_du_isqrt; inv = d_du_inv; n = NU; cb = b; segbase = 0; }
    else         { deg = d_deg_i; degw = d_deg_i; rp = d_rpi; cur = d_curi; isq = d_di_isqrt; inv = d_di_inv; n = NI; cb = b - PBU; segbase = PBU; }

    int t = threadIdx.x;
    int pv = (t < NPART && t >= segbase && t < b) ? d_part[t] : 0;
    #pragma unroll
    for (int m = 16; m >= 1; m >>= 1) pv += __shfl_xor_sync(0xffffffffu, pv, m);
    __shared__ int sw[8];
    __shared__ int blockoff;
    if ((t & 31) == 0) sw[t >> 5] = pv;
    __syncthreads();
    if (t == 0) {
        int s = 0;
        #pragma unroll
        for (int w = 0; w < 8; w++) s += sw[w];
        blockoff = s;
        if (b == 0)   d_rpu[NU] = NE;
        if (b == PBU) d_rpi[NI] = NE;
    }

    int base = cb * CHUNK;
    int idx0 = base + t * 4;
    int v[4]; int tsum = 0;
    #pragma unroll
    for (int j = 0; j < 4; j++) {
        v[j] = (idx0 + j < n) ? deg[idx0 + j] : 0;
        tsum += v[j];
    }
    __shared__ int s[256];
    s[t] = tsum;
    __syncthreads();
    #pragma unroll
    for (int off = 1; off < 256; off <<= 1) {
        int add = (t >= off) ? s[t - off] : 0;
        __syncthreads();
        s[t] += add;
        __syncthreads();
    }
    int off0 = blockoff + (s[t] - tsum);
    int run = 0;
    #pragma unroll
    for (int j = 0; j < 4; j++) {
        int idx = idx0 + j;
        if (idx < n) {
            rp[idx] = off0 + run;
            cur[idx] = off0 + run;
            int dg = v[j];
            isq[idx] = (dg > 0) ? rsqrtf((float)dg) : 0.0f;
            inv[idx] = (dg > 0) ? 1.0f / (float)dg : 0.0f;
            degw[idx] = 0;     // self-clean for next graph replay
            run += dg;
        }
    }
}

// merged: CSR fill + Xh init
__global__ void k_fill_init(const int* __restrict__ eu, const int* __restrict__ ei,
                            const float* __restrict__ u_emb, const float* __restrict__ i_emb) {
    if (blockIdx.x < FILL_BLOCKS) {
        int e = blockIdx.x * blockDim.x + threadIdx.x;
        if (e < NE) {
            int u = eu[e], it = ei[e];
            int pu = atomicAdd(&d_curu[u], 1);
            d_colu[pu] = it;
            int pi = atomicAdd(&d_curi[it], 1);
            d_coli[pi] = u;
        }
    } else {
        int gt = (blockIdx.x - FILL_BLOCKS) * blockDim.x + threadIdx.x;
        if (gt < NV * 16) {
            int r = gt >> 4;
            float4 x = (r < NU) ? ((const float4*)u_emb)[gt]
                                : ((const float4*)i_emb)[gt - NU * 16];
            float s = (r < NU) ? d_du_isqrt[r] : d_di_isqrt[r - NU];
            float4 xs;
            xs.x = x.x * s; xs.y = x.y * s; xs.z = x.z * s; xs.w = x.w * s;
            d_Xh[gt] = f4_to_h4(xs);
        }
    }
}

// ---------------- gather core: 4 independent loads, 2 accumulator pairs (DO NOT TOUCH) ----------------
__device__ __forceinline__ void gather_row8(const int* __restrict__ col,
                                            const uint4* __restrict__ tab,
                                            int s, int e, int lane,
                                            float4& olo, float4& ohi) {
    float4 l0 = {0,0,0,0}, h0 = {0,0,0,0};
    float4 l1 = {0,0,0,0}, h1 = {0,0,0,0};
    int p = s;
    for (; p + 3 < e; p += 4) {
        int n0 = __ldg(&col[p]);
        int n1 = __ldg(&col[p + 1]);
        int n2 = __ldg(&col[p + 2]);
        int n3 = __ldg(&col[p + 3]);
        uint4 x0 = __ldg(&tab[n0 * 8 + lane]);
        uint4 x1 = __ldg(&tab[n1 * 8 + lane]);
        uint4 x2 = __ldg(&tab[n2 * 8 + lane]);
        uint4 x3 = __ldg(&tab[n3 * 8 + lane]);
        h8_acc(x0, l0, h0);
        h8_acc(x1, l1, h1);
        h8_acc(x2, l0, h0);
        h8_acc(x3, l1, h1);
    }
    for (; p < e; p++) {
        int n0 = __ldg(&col[p]);
        uint4 x0 = __ldg(&tab[n0 * 8 + lane]);
        h8_acc(x0, l0, h0);
    }
    olo.x = l0.x + l1.x; olo.y = l0.y + l1.y; olo.z = l0.z + l1.z; olo.w = l0.w + l1.w;
    ohi.x = h0.x + h1.x; ohi.y = h0.y + h1.y; ohi.z = h0.z + h1.z; ohi.w = h0.w + h1.w;
}

// ---------------- smoothing pass 1: Sh from Xh ----------------
__global__ void __launch_bounds__(256) k_smoothA() {
    int gt = blockIdx.x * blockDim.x + threadIdx.x;
    int qw = gt >> 3, lane = gt & 7;
    if (qw >= NV) return;

    const int* col; const uint4* tab; int s, e; float sc; int outr;
    if (qw < NI) {          // items gather users
        int v = qw;
        s = d_rpi[v]; e = d_rpi[v + 1];
        col = d_coli; tab = d_Xh4;
        sc = d_di_inv[v]; outr = v;
    } else {                // users gather items
        int v = qw - NI;
        s = d_rpu[v]; e = d_rpu[v + 1];
        col = d_colu; tab = d_Xh4 + (size_t)NU * 8;
        sc = d_du_inv[v]; outr = NI + v;
    }
    float4 lo, hi;
    gather_row8(col, tab, s, e, lane, lo, hi);
    lo.x *= sc; lo.y *= sc; lo.z *= sc; lo.w *= sc;
    hi.x *= sc; hi.y *= sc; hi.z *= sc; hi.w *= sc;
    d_Sh4[outr * 8 + lane] = f8_to_h8(lo, hi);
}

// ---------------- fused: smoothB gather + dual wmma GEMM + epilogue ----------------
#define LDH 72
#define LDF 68
#define OFF_G   0
#define OFF_H   (OFF_G + 64 * LDH)
#define OFF_WG  (OFF_H + 64 * LDH)
#define OFF_WB  (OFF_WG + 64 * LDH)
#define HALVES_TOTAL (OFF_WB + 64 * LDH)
#define OFF_X   0
#define OFF_CG  (OFF_X + 64 * LDF)
#define OFF_CB  (OFF_CG + 64 * LDF)
#define OFF_BG  (OFF_CB + 64 * LDF)
#define OFF_BB  (OFF_BG + 64)
#define FLOATS_TOTAL (OFF_BB + 64)
#define SMEM_BYTES (HALVES_TOTAL * 2 + FLOATS_TOTAL * 4)

__global__ void __launch_bounds__(512) k_layer(
        const float* __restrict__ Wgc, const float* __restrict__ bgc,
        const float* __restrict__ Wbi, const float* __restrict__ bbi,
        const float* __restrict__ xu, const float* __restrict__ xi,
        int l, int write_xs, int first, int final, float* __restrict__ outp) {
    extern __shared__ __align__(16) char smraw[];
    __half* sH_base = (__half*)smraw;
    float*  sF_base = (float*)(smraw + HALVES_TOTAL * 2);
    __half* sG  = sH_base + OFF_G;
    __half* sHm = sH_base + OFF_H;
    __half* sWg = sH_base + OFF_WG;
    __half* sWb = sH_base + OFF_WB;
    float*  sX  = sF_base + OFF_X;
    float*  sCg = sF_base + OFF_CG;
    float*  sCb = sF_base + OFF_CB;
    float*  sbg = sF_base + OFF_BG;
    float*  sbb = sF_base + OFF_BB;

    int t = threadIdx.x;          // 512 threads
    int row0 = blockIdx.x * 64;

    // --- stage weights + biases ---
    const float* Wg = Wgc + l * 4096;
    const float* Wb = Wbi + l * 4096;
    #pragma unroll
    for (int i = t; i < 64 * 16; i += 512) {
        int dd = i >> 4, kq = i & 15;
        float4 wg4 = __ldg((const float4*)&Wg[dd * 64 + kq * 4]);
        float4 wb4 = __ldg((const float4*)&Wb[dd * 64 + kq * 4]);
        *(uint2*)&sWg[dd * LDH + kq * 4] = f4_to_h4(wg4);
        *(uint2*)&sWb[dd * LDH + kq * 4] = f4_to_h4(wb4);
    }
    if (t < 64) {
        sbg[t] = bgc[l * 64 + t];
        sbb[t] = bbi[l * 64 + t];
    }

    // --- phase 1: smoothB gather for this block's 64 rows ---
    {
        int grp = t >> 3, lane = t & 7;   // grp in [0,64)
        int gr = row0 + grp;
        float4 lo = {0,0,0,0}, hi = {0,0,0,0};
        if (gr < NV) {
            const int* col; const uint4* tab; int s, e; float sc;
            if (gr < NU) {       // user gathers item-E rows
                s = d_rpu[gr]; e = d_rpu[gr + 1];
                col = d_colu; tab = d_Sh4;
                sc = d_du_isqrt[gr];
            } else {             // item gathers user-F rows
                int v = gr - NU;
                s = d_rpi[v]; e = d_rpi[v + 1];
                col = d_coli; tab = d_Sh4 + (size_t)NI * 8;
                sc = d_di_isqrt[v];
            }
            gather_row8(col, tab, s, e, lane, lo, hi);
            lo.x *= sc; lo.y *= sc; lo.z *= sc; lo.w *= sc;
            hi.x *= sc; hi.y *= sc; hi.z *= sc; hi.w *= sc;
        }
        uint4 gq = f8_to_h8(lo, hi);
        *(uint4*)&sG[grp * LDH + lane * 8] = gq;

        float4 xa = {0,0,0,0}, xb = {0,0,0,0};
        if (gr < NV) {
            const float4* xrow = (gr < NU) ? (const float4*)(xu + (size_t)gr * 64)
                                           : (const float4*)(xi + (size_t)(gr - NU) * 64);
            xa = __ldg(&xrow[lane * 2]);
            xb = __ldg(&xrow[lane * 2 + 1]);
        }
        *(float4*)&sX[grp * LDF + lane * 8]     = xa;
        *(float4*)&sX[grp * LDF + lane * 8 + 4] = xb;
        float4 gfa = h4_to_f4(make_uint2(gq.x, gq.y));
        float4 gfb = h4_to_f4(make_uint2(gq.z, gq.w));
        float4 ha, hb;
        ha.x = gfa.x * xa.x; ha.y = gfa.y * xa.y; ha.z = gfa.z * xa.z; ha.w = gfa.w * xa.w;
        hb.x = gfb.x * xb.x; hb.y = gfb.y * xb.y; hb.z = gfb.z * xb.z; hb.w = gfb.w * xb.w;
        uint2 h0 = f4_to_h4(ha), h1 = f4_to_h4(hb);
        uint4 hq = make_uint4(h0.x, h0.y, h1.x, h1.y);
        *(uint4*)&sHm[grp * LDH + lane * 8] = hq;
    }
    __syncthreads();

    // --- phase 2: wmma, 16 warps ---
    {
        int w = t >> 5;               // 0..15
        int sel = w >> 3;             // 0: Cg, 1: Cb
        int sub = w & 7;
        int nt = sub & 3;             // n-tile
        int mh = sub >> 2;            // m-half
        const __half* A = sel ? sHm : sG;
        const __half* B = sel ? sWb : sWg;
        float* C = sel ? sCb : sCg;

        wmma::fragment<wmma::accumulator, 16, 16, 16, float> acc[2];
        #pragma unroll
        for (int m = 0; m < 2; m++) wmma::fill_fragment(acc[m], 0.0f);

        #pragma unroll
        for (int k = 0; k < 4; k++) {
            wmma::fragment<wmma::matrix_b, 16, 16, 16, __half, wmma::col_major> bf;
            wmma::load_matrix_sync(bf, B + nt * 16 * LDH + k * 16, LDH);
            #pragma unroll
            for (int m = 0; m < 2; m++) {
                wmma::fragment<wmma::matrix_a, 16, 16, 16, __half, wmma::row_major> af;
                wmma::load_matrix_sync(af, A + (mh * 2 + m) * 16 * LDH + k * 16, LDH);
                wmma::mma_sync(acc[m], af, bf, acc[m]);
            }
        }
        #pragma unroll
        for (int m = 0; m < 2; m++)
            wmma::store_matrix_sync(C + (mh * 2 + m) * 16 * LDF + nt * 16, acc[m], LDF,
                                    wmma::mem_row_major);
    }
    __syncthreads();

    // --- phase 3: epilogue (512 threads, 2 rows each) ---
    int tx = t & 15, ty = t >> 4;     // ty in [0,32)
    int c0 = tx * 4, r0 = ty * 2;

    #pragma unroll
    for (int i = 0; i < 2; i++) {
        float vj[4];
        float ssq = 0.f;
        #pragma unroll
        for (int j = 0; j < 4; j++) {
            float sg = sCg[(r0 + i) * LDF + c0 + j] + sbg[c0 + j] + sX[(r0 + i) * LDF + c0 + j];
            sg = (sg > 0.f) ? sg : 0.2f * sg;
            float sb = sCb[(r0 + i) * LDF + c0 + j] + sbb[c0 + j];
            sb = (sb > 0.f) ? sb : 0.2f * sb;
            float v = sg + sb;
            vj[j] = v;
            ssq += v * v;
        }
        #pragma unroll
        for (int m = 8; m >= 1; m >>= 1)
            ssq += __shfl_xor_sync(0xffffffffu, ssq, m);
        float inv = 1.0f / fmaxf(sqrtf(ssq), 1e-12f);
        int gr = row0 + r0 + i;
        if (gr < NV) {
            float4 o;
            o.x = vj[0] * inv; o.y = vj[1] * inv; o.z = vj[2] * inv; o.w = vj[3] * inv;
            float4 a;
            if (first) {
                a.x = sX[(r0 + i) * LDF + c0 + 0];
                a.y = sX[(r0 + i) * LDF + c0 + 1];
                a.z = sX[(r0 + i) * LDF + c0 + 2];
                a.w = sX[(r0 + i) * LDF + c0 + 3];
            } else {
                a = *(float4*)&d_acc[gr * 64 + c0];
            }
            a.x += o.x; a.y += o.y; a.z += o.z; a.w += o.w;
            if (final) {
                float4 ov;
                ov.x = a.x * 0.25f; ov.y = a.y * 0.25f; ov.z = a.z * 0.25f; ov.w = a.w * 0.25f;
                *(float4*)&outp[gr * 64 + c0] = ov;
            } else {
                *(float4*)&d_X[gr * 64 + c0] = o;
                *(float4*)&d_acc[gr * 64 + c0] = a;
                if (write_xs) {
                    float srow = (gr < NU) ? d_du_isqrt[gr] : d_di_isqrt[gr - NU];
                    float4 xs;
                    xs.x = o.x * srow; xs.y = o.y * srow; xs.z = o.z * srow; xs.w = o.w * srow;
                    d_Xh[gr * 16 + (c0 >> 2)] = f4_to_h4(xs);
                }
            }
        }
    }
}

// ---------------- launch ----------------
extern "C" void kernel_launch(void* const* d_in, const int* in_sizes, int n_in,
                              void* d_out, int out_size) {
    const float* u_emb = (const float*)d_in[0];
    const float* i_emb = (const float*)d_in[1];
    const float* Wgc   = (const float*)d_in[2];
    const float* bgc   = (const float*)d_in[3];
    const float* Wbi   = (const float*)d_in[4];
    const float* bbi   = (const float*)d_in[5];
    const int*   eu    = (const int*)d_in[6];
    const int*   ei    = (const int*)d_in[7];
    float* out = (float*)d_out;

    cudaFuncSetAttribute(k_layer, cudaFuncAttributeMaxDynamicSharedMemorySize, SMEM_BYTES);

    // degrees are zero on entry: BSS-zero on first (correctness) run,
    // and k_down re-zeroes them at the end of every run thereafter.
    k_degree<<<(NE / 2 + 255) / 256, 256>>>(eu, ei);
    k_part<<<NPART, 256>>>();
    k_down<<<NPART, 256>>>();
    k_fill_init<<<FILL_BLOCKS + INIT_BLOCKS, 256>>>(eu, ei, u_emb, i_emb);

    void* p_X = nullptr;
    cudaGetSymbolAddress(&p_X, d_X);

    for (int l = 0; l < NL; l++) {
        const float* xu = (l == 0) ? u_emb : (const float*)p_X;
        const float* xi = (l == 0) ? i_emb : (const float*)p_X + (size_t)NU * D;
        k_smoothA<<<(NV * 8 + 255) / 256, 256>>>();
        k_layer<<<(NV + 63) / 64, 512, SMEM_BYTES>>>(
            Wgc, bgc, Wbi, bbi, xu, xi, l,
            (l < NL - 1) ? 1 : 0,          // write_xs
            (l == 0) ? 1 : 0,              // first
            (l == NL - 1) ? 1 : 0,         // final
            out);
    }
}

// round 16
// speedup vs baseline: 1.3615x; 1.3615x over previous
#include <cuda_runtime.h>
#include <cuda_fp16.h>
#include <mma.h>

using namespace nvcuda;

#define NU 100000
#define NI 50000
#define NV 150000
#define D  64
#define NE 1000000
#define NL 3

#define CHUNK 1024
#define PBU ((NU + CHUNK - 1) / CHUNK)   // 98
#define PBI ((NI + CHUNK - 1) / CHUNK)   // 49
#define NPART (PBU + PBI)                // 147

#define FILL_BLOCKS ((NE + 255) / 256)       // 3907
#define INIT_BLOCKS ((NV * 16 + 255) / 256)  // 9375

// ---------------- static device scratch ----------------
__device__ float d_X[NV * D];      // current layer embeddings (fp32)
__device__ float d_acc[NV * D];    // running sum of layer embeddings
__device__ uint4 d_Xh4[NV * 8];    // X * dv_isqrt (fp16 rows)
__device__ uint4 d_Sh4[NV * 8];    // mid-hop: E(items) [0..NI), F(users) [NI..NV)
__device__ int   d_deg_u[NU], d_deg_i[NI];
__device__ float d_du_isqrt[NU], d_du_inv[NU];
__device__ float d_di_isqrt[NI], d_di_inv[NI];
__device__ int   d_rpu[NU + 1], d_rpi[NI + 1];
__device__ int   d_curu[NU], d_curi[NI];
__device__ int   d_colu[NE];       // items, grouped by user
__device__ int   d_coli[NE];       // users, grouped by item
__device__ int   d_part[256];

#define d_Xh ((uint2*)d_Xh4)

// ---------------- helpers ----------------
__device__ __forceinline__ float4 h4_to_f4(uint2 q) {
    __half2 h0 = *(__half2*)&q.x;
    __half2 h1 = *(__half2*)&q.y;
    float2 f0 = __half22float2(h0);
    float2 f1 = __half22float2(h1);
    return make_float4(f0.x, f0.y, f1.x, f1.y);
}
__device__ __forceinline__ uint2 f4_to_h4(float4 f) {
    __half2 h0 = __floats2half2_rn(f.x, f.y);
    __half2 h1 = __floats2half2_rn(f.z, f.w);
    uint2 q;
    q.x = *(unsigned*)&h0;
    q.y = *(unsigned*)&h1;
    return q;
}
__device__ __forceinline__ void h8_acc(uint4 q, float4& lo, float4& hi) {
    __half2* h = (__half2*)&q;
    float2 f0 = __half22float2(h[0]);
    float2 f1 = __half22float2(h[1]);
    float2 f2 = __half22float2(h[2]);
    float2 f3 = __half22float2(h[3]);
    lo.x += f0.x; lo.y += f0.y; lo.z += f1.x; lo.w += f1.y;
    hi.x += f2.x; hi.y += f2.y; hi.z += f3.x; hi.w += f3.y;
}
__device__ __forceinline__ uint4 f8_to_h8(float4 lo, float4 hi) {
    uint4 q;
    __half2 h0 = __floats2half2_rn(lo.x, lo.y);
    __half2 h1 = __floats2half2_rn(lo.z, lo.w);
    __half2 h2 = __floats2half2_rn(hi.x, hi.y);
    __half2 h3 = __floats2half2_rn(hi.z, hi.w);
    q.x = *(unsigned*)&h0; q.y = *(unsigned*)&h1;
    q.z = *(unsigned*)&h2; q.w = *(unsigned*)&h3;
    return q;
}

// ---------------- setup ----------------
__global__ void k_degree(const int* __restrict__ eu, const int* __restrict__ ei) {
    int e = blockIdx.x * blockDim.x + threadIdx.x;
    if (e < NE) {
        atomicAdd(&d_deg_u[eu[e]], 1);
        atomicAdd(&d_deg_i[ei[e]], 1);
    }
}

__global__ void k_part() {
    int b = blockIdx.x;
    const int* deg; int n; int cb;
    if (b < PBU) { deg = d_deg_u; n = NU; cb = b; }
    else         { deg = d_deg_i; n = NI; cb = b - PBU; }
    int base = cb * CHUNK;
    int t = threadIdx.x;
    int tsum = 0;
    #pragma unroll
    for (int j = 0; j < 4; j++) {
        int idx = base + t * 4 + j;
        if (idx < n) tsum += deg[idx];
    }
    #pragma unroll
    for (int m = 16; m >= 1; m >>= 1) tsum += __shfl_xor_sync(0xffffffffu, tsum, m);
    __shared__ int sw[8];
    if ((t & 31) == 0) sw[t >> 5] = tsum;
    __syncthreads();
    if (t == 0) {
        int s = 0;
        #pragma unroll
        for (int w = 0; w < 8; w++) s += sw[w];
        d_part[b] = s;
    }
}

// k_down with inline segment-prefix of the partials
__global__ void k_down() {
    int b = blockIdx.x;
    const int* deg; int* rp; int* cur; float* isq; float* inv; int n; int cb; int segbase;
    if (b < PBU) { deg = d_deg_u; rp = d_rpu; cur = d_curu; isq = d_du_isqrt; inv = d_du_inv; n = NU; cb = b; segbase = 0; }
    else         { deg = d_deg_i; rp = d_rpi; cur = d_curi; isq = d_di_isqrt; inv = d_di_inv; n = NI; cb = b - PBU; segbase = PBU; }

    int t = threadIdx.x;
    int pv = (t < NPART && t >= segbase && t < b) ? d_part[t] : 0;
    #pragma unroll
    for (int m = 16; m >= 1; m >>= 1) pv += __shfl_xor_sync(0xffffffffu, pv, m);
    __shared__ int sw[8];
    __shared__ int blockoff;
    if ((t & 31) == 0) sw[t >> 5] = pv;
    __syncthreads();
    if (t == 0) {
        int s = 0;
        #pragma unroll
        for (int w = 0; w < 8; w++) s += sw[w];
        blockoff = s;
        if (b == 0)   d_rpu[NU] = NE;
        if (b == PBU) d_rpi[NI] = NE;
    }

    int base = cb * CHUNK;
    int idx0 = base + t * 4;
    int v[4]; int tsum = 0;
    #pragma unroll
    for (int j = 0; j < 4; j++) {
        v[j] = (idx0 + j < n) ? deg[idx0 + j] : 0;
        tsum += v[j];
    }
    __shared__ int s[256];
    s[t] = tsum;
    __syncthreads();
    #pragma unroll
    for (int off = 1; off < 256; off <<= 1) {
        int add = (t >= off) ? s[t - off] : 0;
        __syncthreads();
        s[t] += add;
        __syncthreads();
    }
    int off0 = blockoff + (s[t] - tsum);
    int run = 0;
    #pragma unroll
    for (int j = 0; j < 4; j++) {
        int idx = idx0 + j;
        if (idx < n) {
            rp[idx] = off0 + run;
            cur[idx] = off0 + run;
            int dg = v[j];
            isq[idx] = (dg > 0) ? rsqrtf((float)dg) : 0.0f;
            inv[idx] = (dg > 0) ? 1.0f / (float)dg : 0.0f;
            run += dg;
        }
    }
}

// merged: CSR fill + Xh init (Xh only — X/acc copies deleted)
__global__ void k_fill_init(const int* __restrict__ eu, const int* __restrict__ ei,
                            const float* __restrict__ u_emb, const float* __restrict__ i_emb) {
    if (blockIdx.x < FILL_BLOCKS) {
        int e = blockIdx.x * blockDim.x + threadIdx.x;
        if (e < NE) {
            int u = eu[e], it = ei[e];
            int pu = atomicAdd(&d_curu[u], 1);
            d_colu[pu] = it;
            int pi = atomicAdd(&d_curi[it], 1);
            d_coli[pi] = u;
        }
    } else {
        int gt = (blockIdx.x - FILL_BLOCKS) * blockDim.x + threadIdx.x;
        if (gt < NV * 16) {
            int r = gt >> 4;
            float4 x = (r < NU) ? ((const float4*)u_emb)[gt]
                                : ((const float4*)i_emb)[gt - NU * 16];
            float s = (r < NU) ? d_du_isqrt[r] : d_di_isqrt[r - NU];
            float4 xs;
            xs.x = x.x * s; xs.y = x.y * s; xs.z = x.z * s; xs.w = x.w * s;
            d_Xh[gt] = f4_to_h4(xs);
        }
    }
}

// ---------------- gather core: 4 independent loads, 2 accumulator pairs ----------------
__device__ __forceinline__ void gather_row8(const int* __restrict__ col,
                                            const uint4* __restrict__ tab,
                                            int s, int e, int lane,
                                            float4& olo, float4& ohi) {
    float4 l0 = {0,0,0,0}, h0 = {0,0,0,0};
    float4 l1 = {0,0,0,0}, h1 = {0,0,0,0};
    int p = s;
    for (; p + 3 < e; p += 4) {
        int n0 = __ldg(&col[p]);
        int n1 = __ldg(&col[p + 1]);
        int n2 = __ldg(&col[p + 2]);
        int n3 = __ldg(&col[p + 3]);
        uint4 x0 = __ldg(&tab[n0 * 8 + lane]);
        uint4 x1 = __ldg(&tab[n1 * 8 + lane]);
        uint4 x2 = __ldg(&tab[n2 * 8 + lane]);
        uint4 x3 = __ldg(&tab[n3 * 8 + lane]);
        h8_acc(x0, l0, h0);
        h8_acc(x1, l1, h1);
        h8_acc(x2, l0, h0);
        h8_acc(x3, l1, h1);
    }
    for (; p < e; p++) {
        int n0 = __ldg(&col[p]);
        uint4 x0 = __ldg(&tab[n0 * 8 + lane]);
        h8_acc(x0, l0, h0);
    }
    olo.x = l0.x + l1.x; olo.y = l0.y + l1.y; olo.z = l0.z + l1.z; olo.w = l0.w + l1.w;
    ohi.x = h0.x + h1.x; ohi.y = h0.y + h1.y; ohi.z = h0.z + h1.z; ohi.w = h0.w + h1.w;
}

// ---------------- smoothing pass 1: Sh from Xh ----------------
__global__ void __launch_bounds__(256) k_smoothA() {
    int gt = blockIdx.x * blockDim.x + threadIdx.x;
    int qw = gt >> 3, lane = gt & 7;
    if (qw >= NV) return;

    const int* col; const uint4* tab; int s, e; float sc; int outr;
    if (qw < NI) {          // items gather users
        int v = qw;
        s = d_rpi[v]; e = d_rpi[v + 1];
        col = d_coli; tab = d_Xh4;
        sc = d_di_inv[v]; outr = v;
    } else {                // users gather items
        int v = qw - NI;
        s = d_rpu[v]; e = d_rpu[v + 1];
        col = d_colu; tab = d_Xh4 + (size_t)NU * 8;
        sc = d_du_inv[v]; outr = NI + v;
    }
    float4 lo, hi;
    gather_row8(col, tab, s, e, lane, lo, hi);
    lo.x *= sc; lo.y *= sc; lo.z *= sc; lo.w *= sc;
    hi.x *= sc; hi.y *= sc; hi.z *= sc; hi.w *= sc;
    d_Sh4[outr * 8 + lane] = f8_to_h8(lo, hi);
}

// ---------------- fused: smoothB gather + dual wmma GEMM + epilogue ----------------
#define LDH 72
#define LDF 68
#define OFF_G   0
#define OFF_H   (OFF_G + 64 * LDH)
#define OFF_WG  (OFF_H + 64 * LDH)
#define OFF_WB  (OFF_WG + 64 * LDH)
#define HALVES_TOTAL (OFF_WB + 64 * LDH)
#define OFF_X   0
#define OFF_CG  (OFF_X + 64 * LDF)
#define OFF_CB  (OFF_CG + 64 * LDF)
#define OFF_BG  (OFF_CB + 64 * LDF)
#define OFF_BB  (OFF_BG + 64)
#define FLOATS_TOTAL (OFF_BB + 64)
#define SMEM_BYTES (HALVES_TOTAL * 2 + FLOATS_TOTAL * 4)

__global__ void __launch_bounds__(512) k_layer(
        const float* __restrict__ Wgc, const float* __restrict__ bgc,
        const float* __restrict__ Wbi, const float* __restrict__ bbi,
        const float* __restrict__ xu, const float* __restrict__ xi,
        int l, int write_xs, int first, int final, float* __restrict__ outp) {
    extern __shared__ __align__(16) char smraw[];
    __half* sH_base = (__half*)smraw;
    float*  sF_base = (float*)(smraw + HALVES_TOTAL * 2);
    __half* sG  = sH_base + OFF_G;
    __half* sHm = sH_base + OFF_H;
    __half* sWg = sH_base + OFF_WG;
    __half* sWb = sH_base + OFF_WB;
    float*  sX  = sF_base + OFF_X;
    float*  sCg = sF_base + OFF_CG;
    float*  sCb = sF_base + OFF_CB;
    float*  sbg = sF_base + OFF_BG;
    float*  sbb = sF_base + OFF_BB;

    int t = threadIdx.x;          // 512 threads
    int row0 = blockIdx.x * 64;

    // --- stage weights + biases ---
    const float* Wg = Wgc + l * 4096;
    const float* Wb = Wbi + l * 4096;
    #pragma unroll
    for (int i = t; i < 64 * 16; i += 512) {
        int dd = i >> 4, kq = i & 15;
        float4 wg4 = __ldg((const float4*)&Wg[dd * 64 + kq * 4]);
        float4 wb4 = __ldg((const float4*)&Wb[dd * 64 + kq * 4]);
        *(uint2*)&sWg[dd * LDH + kq * 4] = f4_to_h4(wg4);
        *(uint2*)&sWb[dd * LDH + kq * 4] = f4_to_h4(wb4);
    }
    if (t < 64) {
        sbg[t] = bgc[l * 64 + t];
        sbb[t] = bbi[l * 64 + t];
    }

    // --- phase 1: smoothB gather for this block's 64 rows ---
    {
        int grp = t >> 3, lane = t & 7;   // grp in [0,64)
        int gr = row0 + grp;
        float4 lo = {0,0,0,0}, hi = {0,0,0,0};
        if (gr < NV) {
            const int* col; const uint4* tab; int s, e; float sc;
            if (gr < NU) {       // user gathers item-E rows
                s = d_rpu[gr]; e = d_rpu[gr + 1];
                col = d_colu; tab = d_Sh4;
                sc = d_du_isqrt[gr];
            } else {             // item gathers user-F rows
                int v = gr - NU;
                s = d_rpi[v]; e = d_rpi[v + 1];
                col = d_coli; tab = d_Sh4 + (size_t)NI * 8;
                sc = d_di_isqrt[v];
            }
            gather_row8(col, tab, s, e, lane, lo, hi);
            lo.x *= sc; lo.y *= sc; lo.z *= sc; lo.w *= sc;
            hi.x *= sc; hi.y *= sc; hi.z *= sc; hi.w *= sc;
        }
        uint4 gq = f8_to_h8(lo, hi);
        *(uint4*)&sG[grp * LDH + lane * 8] = gq;

        float4 xa = {0,0,0,0}, xb = {0,0,0,0};
        if (gr < NV) {
            const float4* xrow = (gr < NU) ? (const float4*)(xu + (size_t)gr * 64)
                                           : (const float4*)(xi + (size_t)(gr - NU) * 64);
            xa = __ldg(&xrow[lane * 2]);
            xb = __ldg(&xrow[lane * 2 + 1]);
        }
        *(float4*)&sX[grp * LDF + lane * 8]     = xa;
        *(float4*)&sX[grp * LDF + lane * 8 + 4] = xb;
        float4 gfa = h4_to_f4(make_uint2(gq.x, gq.y));
        float4 gfb = h4_to_f4(make_uint2(gq.z, gq.w));
        float4 ha, hb;
        ha.x = gfa.x * xa.x; ha.y = gfa.y * xa.y; ha.z = gfa.z * xa.z; ha.w = gfa.w * xa.w;
        hb.x = gfb.x * xb.x; hb.y = gfb.y * xb.y; hb.z = gfb.z * xb.z; hb.w = gfb.w * xb.w;
        uint2 h0 = f4_to_h4(ha), h1 = f4_to_h4(hb);
        uint4 hq = make_uint4(h0.x, h0.y, h1.x, h1.y);
        *(uint4*)&sHm[grp * LDH + lane * 8] = hq;
    }
    __syncthreads();

    // --- phase 2: wmma, 16 warps ---
    {
        int w = t >> 5;               // 0..15
        int sel = w >> 3;             // 0: Cg, 1: Cb
        int sub = w & 7;
        int nt = sub & 3;             // n-tile
        int mh = sub >> 2;            // m-half
        const __half* A = sel ? sHm : sG;
        const __half* B = sel ? sWb : sWg;
        float* C = sel ? sCb : sCg;

        wmma::fragment<wmma::accumulator, 16, 16, 16, float> acc[2];
        #pragma unroll
        for (int m = 0; m < 2; m++) wmma::fill_fragment(acc[m], 0.0f);

        #pragma unroll
        for (int k = 0; k < 4; k++) {
            wmma::fragment<wmma::matrix_b, 16, 16, 16, __half, wmma::col_major> bf;
            wmma::load_matrix_sync(bf, B + nt * 16 * LDH + k * 16, LDH);
            #pragma unroll
            for (int m = 0; m < 2; m++) {
                wmma::fragment<wmma::matrix_a, 16, 16, 16, __half, wmma::row_major> af;
                wmma::load_matrix_sync(af, A + (mh * 2 + m) * 16 * LDH + k * 16, LDH);
                wmma::mma_sync(acc[m], af, bf, acc[m]);
            }
        }
        #pragma unroll
        for (int m = 0; m < 2; m++)
            wmma::store_matrix_sync(C + (mh * 2 + m) * 16 * LDF + nt * 16, acc[m], LDF,
                                    wmma::mem_row_major);
    }
    __syncthreads();

    // --- phase 3: epilogue (512 threads, 2 rows each) ---
    int tx = t & 15, ty = t >> 4;     // ty in [0,32)
    int c0 = tx * 4, r0 = ty * 2;

    #pragma unroll
    for (int i = 0; i < 2; i++) {
        float vj[4];
        float ssq = 0.f;
        #pragma unroll
        for (int j = 0; j < 4; j++) {
            float sg = sCg[(r0 + i) * LDF + c0 + j] + sbg[c0 + j] + sX[(r0 + i) * LDF + c0 + j];
            sg = (sg > 0.f) ? sg : 0.2f * sg;
            float sb = sCb[(r0 + i) * LDF + c0 + j] + sbb[c0 + j];
            sb = (sb > 0.f) ? sb : 0.2f * sb;
            float v = sg + sb;
            vj[j] = v;
            ssq += v * v;
        }
        #pragma unroll
        for (int m = 8; m >= 1; m >>= 1)
            ssq += __shfl_xor_sync(0xffffffffu, ssq, m);
        float inv = 1.0f / fmaxf(sqrtf(ssq), 1e-12f);
        int gr = row0 + r0 + i;
        if (gr < NV) {
            float4 o;
            o.x = vj[0] * inv; o.y = vj[1] * inv; o.z = vj[2] * inv; o.w = vj[3] * inv;
            float4 a;
            if (first) {
                // acc_prev == X (layer 0), already staged in shared
                a.x = sX[(r0 + i) * LDF + c0 + 0];
                a.y = sX[(r0 + i) * LDF + c0 + 1];
                a.z = sX[(r0 + i) * LDF + c0 + 2];
                a.w = sX[(r0 + i) * LDF + c0 + 3];
            } else {
                a = *(float4*)&d_acc[gr * 64 + c0];
            }
            a.x += o.x; a.y += o.y; a.z += o.z; a.w += o.w;
            if (final) {
                float4 ov;
                ov.x = a.x * 0.25f; ov.y = a.y * 0.25f; ov.z = a.z * 0.25f; ov.w = a.w * 0.25f;
                *(float4*)&outp[gr * 64 + c0] = ov;
            } else {
                *(float4*)&d_X[gr * 64 + c0] = o;
                *(float4*)&d_acc[gr * 64 + c0] = a;
                if (write_xs) {
                    float srow = (gr < NU) ? d_du_isqrt[gr] : d_di_isqrt[gr - NU];
                    float4 xs;
                    xs.x = o.x * srow; xs.y = o.y * srow; xs.z = o.z * srow; xs.w = o.w * srow;
                    d_Xh[gr * 16 + (c0 >> 2)] = f4_to_h4(xs);
                }
            }
        }
    }
}

// ---------------- launch ----------------
extern "C" void kernel_launch(void* const* d_in, const int* in_sizes, int n_in,
                              void* d_out, int out_size) {
    const float* u_emb = (const float*)d_in[0];
    const float* i_emb = (const float*)d_in[1];
    const float* Wgc   = (const float*)d_in[2];
    const float* bgc   = (const float*)d_in[3];
    const float* Wbi   = (const float*)d_in[4];
    const float* bbi   = (const float*)d_in[5];
    const int*   eu    = (const int*)d_in[6];
    const int*   ei    = (const int*)d_in[7];
    float* out = (float*)d_out;

    cudaFuncSetAttribute(k_layer, cudaFuncAttributeMaxDynamicSharedMemorySize, SMEM_BYTES);

    void* p_deg_u = nullptr;
    void* p_deg_i = nullptr;
    cudaGetSymbolAddress(&p_deg_u, d_deg_u);
    cudaGetSymbolAddress(&p_deg_i, d_deg_i);
    cudaMemsetAsync(p_deg_u, 0, NU * sizeof(int), 0);
    cudaMemsetAsync(p_deg_i, 0, NI * sizeof(int), 0);

    k_degree<<<(NE + 255) / 256, 256>>>(eu, ei);
    k_part<<<NPART, 256>>>();
    k_down<<<NPART, 256>>>();
    k_fill_init<<<FILL_BLOCKS + INIT_BLOCKS, 256>>>(eu, ei, u_emb, i_emb);

    void* p_X = nullptr;
    cudaGetSymbolAddress(&p_X, d_X);

    for (int l = 0; l < NL; l++) {
        const float* xu = (l == 0) ? u_emb : (const float*)p_X;
        const float* xi = (l == 0) ? i_emb : (const float*)p_X + (size_t)NU * D;
        k_smoothA<<<(NV * 8 + 255) / 256, 256>>>();
        k_layer<<<(NV + 63) / 64, 512, SMEM_BYTES>>>(
            Wgc, bgc, Wbi, bbi, xu, xi, l,
            (l < NL - 1) ? 1 : 0,          // write_xs
            (l == 0) ? 1 : 0,              // first
            (l == NL - 1) ? 1 : 0,         // final
            out);
    }
}